// round 12
// baseline (speedup 1.0000x reference)
#include <cuda_runtime.h>
#include <cuda_fp16.h>

#define D 128
#define ALPHA 0.1f
#define BETA 0.22314355131420976f        /* log(1.25) */
#define ONE_MB 0.7768564486857909f       /* 1 - BETA */
#define MAXN 50000
#define MAXE 600000
#define SCAN_B 256
#define MAXNB 256

__device__ int      g_deg[MAXN];         // zero at load; re-zeroed every call
__device__ int      g_off[MAXN + 1];
__device__ int      g_cursor[MAXN];
__device__ int      g_csrc[MAXE];
__device__ float    g_norm[MAXN];
__device__ uint2    g_feath[MAXN * 32];  // fp16 prescaled feat: row = 256B
__device__ int      g_bsum[MAXNB];
__device__ uint2    g_wperm[16 * 16 * 32];
__device__ unsigned g_bar1, g_bar2, g_bar3, g_done_ctr;  // zero at load; reset each call

__device__ __forceinline__ unsigned f2tf32(float f) {
    unsigned r;
    asm("cvt.rna.tf32.f32 %0, %1;" : "=r"(r) : "f"(f));
    return r;
}

__device__ __forceinline__ void grid_barrier(unsigned* ctr, unsigned nb) {
    __syncthreads();
    __threadfence();
    if (threadIdx.x == 0) {
        atomicAdd(ctr, 1u);
        while (*(volatile unsigned*)ctr < nb) { }
    }
    __syncthreads();
    __threadfence();
}

// ---- ONE prep kernel: wconv+deg -> scan+norm -> offsets -> permute+prescale ----
// Launched with grid = max(edge blocks, scan blocks, 32); all co-resident.
__global__ __launch_bounds__(256) void prep_kernel(const int* __restrict__ src,
                                                   const int* __restrict__ dst,
                                                   const float* __restrict__ W,
                                                   const float* __restrict__ feat,
                                                   int ne, int n, int nb) {
    __shared__ int s[256];
    __shared__ int wsum[8];
    const int tid = threadIdx.x;
    const int bid = blockIdx.x;
    const unsigned nbk = gridDim.x;

    // P0: W -> tf32 B-fragment permutation (blocks 0..31)
    if (bid < 32) {
        int t = bid * 256 + tid;
        int lane = t & 31, tile = t >> 5;
        int nt = tile & 15, kt = tile >> 4;
        int k = kt * 8 + (lane & 3);
        int nn = nt * 8 + (lane >> 2);
        uint2 b;
        b.x = f2tf32(W[k * D + nn]);
        b.y = f2tf32(W[(k + 4) * D + nn]);
        g_wperm[tile * 32 + lane] = b;
    }
    // P0: degree count, 4 edges/thread (grid-stride outer for safety)
    for (int base = bid * 1024 + tid; base < ne + 1023; base += nbk * 1024) {
        int d0 = -1, d1 = -1, d2 = -1, d3 = -1;
        if (base       < ne) d0 = dst[base];
        if (base + 256 < ne) d1 = dst[base + 256];
        if (base + 512 < ne) d2 = dst[base + 512];
        if (base + 768 < ne) d3 = dst[base + 768];
        if (d0 >= 0) atomicAdd(&g_deg[d0], 1);
        if (d1 >= 0) atomicAdd(&g_deg[d1], 1);
        if (d2 >= 0) atomicAdd(&g_deg[d2], 1);
        if (d3 >= 0) atomicAdd(&g_deg[d3], 1);
    }

    grid_barrier(&g_bar1, nbk);

    // P1a: local scan + norm (blocks < nb)
    const int i = bid * SCAN_B + tid;
    int local_ex = 0;
    if (bid < nb) {
        int v = (i < n) ? g_deg[i] : 0;
        s[tid] = v;
        __syncthreads();
        #pragma unroll
        for (int off = 1; off < SCAN_B; off <<= 1) {
            int t2 = (tid >= off) ? s[tid - off] : 0;
            __syncthreads();
            s[tid] += t2;
            __syncthreads();
        }
        local_ex = s[tid] - v;
        if (i < n) g_norm[i] = rsqrtf(fmaxf((float)v, 1.0f));
        if (tid == SCAN_B - 1) g_bsum[bid] = s[SCAN_B - 1];
    }

    grid_barrier(&g_bar2, nbk);

    // P1b: cross-block prefix, write offsets + cursors
    if (bid < nb) {
        int pv = (tid < bid) ? g_bsum[tid] : 0;
        #pragma unroll
        for (int o = 16; o > 0; o >>= 1) pv += __shfl_down_sync(0xffffffffu, pv, o);
        if ((tid & 31) == 0) wsum[tid >> 5] = pv;
        __syncthreads();
        int prefix = wsum[0] + wsum[1] + wsum[2] + wsum[3]
                   + wsum[4] + wsum[5] + wsum[6] + wsum[7];
        if (i < n) {
            int o = local_ex + prefix;
            g_off[i] = o;
            g_cursor[i] = o;
        }
        if (i == 0) g_off[n] = ne;
    }

    grid_barrier(&g_bar3, nbk);

    // P2: permute edges into CSR (4/thread)
    for (int base = bid * 1024 + tid; base < ne + 1023; base += nbk * 1024) {
        int s0 = 0, s1 = 0, s2 = 0, s3 = 0;
        int d0 = -1, d1 = -1, d2 = -1, d3 = -1;
        if (base       < ne) { s0 = src[base];       d0 = dst[base]; }
        if (base + 256 < ne) { s1 = src[base + 256]; d1 = dst[base + 256]; }
        if (base + 512 < ne) { s2 = src[base + 512]; d2 = dst[base + 512]; }
        if (base + 768 < ne) { s3 = src[base + 768]; d3 = dst[base + 768]; }
        int p0 = (d0 >= 0) ? atomicAdd(&g_cursor[d0], 1) : 0;
        int p1 = (d1 >= 0) ? atomicAdd(&g_cursor[d1], 1) : 0;
        int p2 = (d2 >= 0) ? atomicAdd(&g_cursor[d2], 1) : 0;
        int p3 = (d3 >= 0) ? atomicAdd(&g_cursor[d3], 1) : 0;
        if (d0 >= 0) g_csrc[p0] = s0;
        if (d1 >= 0) g_csrc[p1] = s1;
        if (d2 >= 0) g_csrc[p2] = s2;
        if (d3 >= 0) g_csrc[p3] = s3;
    }
    // P2: prescale feat*norm -> fp16 (grid-stride)
    for (int idx = bid * 256 + tid; idx < n * 32; idx += nbk * 256) {
        int row = idx >> 5;
        float nm = g_norm[row];
        float4 fv = __ldg((const float4*)feat + idx);
        __half2 h0 = __floats2half2_rn(fv.x * nm, fv.y * nm);
        __half2 h1 = __floats2half2_rn(fv.z * nm, fv.w * nm);
        uint2 p;
        p.x = *(unsigned*)&h0;
        p.y = *(unsigned*)&h1;
        g_feath[idx] = p;
    }
    // P2: re-zero deg for next replay
    for (int idx = bid * 256 + tid; idx < n; idx += nbk * 256) g_deg[idx] = 0;

    // last finisher resets barrier counters (graph-replay safe)
    __syncthreads();
    __threadfence();
    if (tid == 0) {
        unsigned dc = atomicAdd(&g_done_ctr, 1u);
        if (dc == nbk - 1) {
            g_bar1 = 0; g_bar2 = 0; g_bar3 = 0; g_done_ctr = 0;
            __threadfence();
        }
    }
}

// ---- FUSED aggregation + tensor-core GEMM, 512 threads / 16 warps ----
// Phase 1: paired-lane gathers — lanes 0-15 edge e, lanes 16-31 edge e+1,
//          LDG.128/lane (1 instr / 2 edges), fp32 accumulate, xor-16 reduce.
// Phase 2: warp -> (M-tile 16 x N-quarter 32), m16n8k8 tf32 MMA.
#define GROWS 64
#define SH_PAD 132   /* mod 32 = 4 -> conflict-free A-frag LDS */
__global__ __launch_bounds__(512, 3) void fused_mma_kernel(const float* __restrict__ feat0,
                                                           const float* __restrict__ bias,
                                                           float* __restrict__ out, int n) {
    __shared__ float sh[GROWS][SH_PAD];
    const int tid  = threadIdx.x;
    const int w    = tid >> 5;
    const int lane = tid & 31;
    const int half = lane >> 4;           // 0 or 1
    const int li   = lane & 15;
    const int r0   = blockIdx.x * GROWS;
    const uint4* f4 = (const uint4*)g_feath;   // row = 16 uint4

    // ---- phase 1: aggregate 4 rows per warp ----
    #pragma unroll
    for (int rr = 0; rr < 4; rr++) {
        int lrow = w * 4 + rr;
        int row  = r0 + lrow;
        if (row < n) {
            float2 a0 = make_float2(0.f, 0.f), a1 = a0, a2 = a0, a3 = a0;
            int beg = g_off[row];
            int end = g_off[row + 1];
            for (int j0 = beg; j0 < end; j0 += 32) {
                int jj = j0 + lane;
                int s = (jj < end) ? g_csrc[jj] : 0;
                int m = min(32, end - j0);
                for (int e = 0; e < m; e += 8) {
                    int e0 = e + half, e1 = e + 2 + half;
                    int e2 = e + 4 + half, e3 = e + 6 + half;
                    int ss0 = __shfl_sync(0xffffffffu, s, min(e0, m - 1));
                    int ss1 = __shfl_sync(0xffffffffu, s, min(e1, m - 1));
                    int ss2 = __shfl_sync(0xffffffffu, s, min(e2, m - 1));
                    int ss3 = __shfl_sync(0xffffffffu, s, min(e3, m - 1));
                    uint4 q0 = make_uint4(0u,0u,0u,0u), q1 = q0, q2 = q0, q3 = q0;
                    if (e0 < m) q0 = __ldg(f4 + (size_t)ss0 * 16 + li);
                    if (e1 < m) q1 = __ldg(f4 + (size_t)ss1 * 16 + li);
                    if (e2 < m) q2 = __ldg(f4 + (size_t)ss2 * 16 + li);
                    if (e3 < m) q3 = __ldg(f4 + (size_t)ss3 * 16 + li);
                    #define ACCUM(q) do { \
                        __half2* ph = (__half2*)&(q); \
                        float2 t0 = __half22float2(ph[0]); \
                        float2 t1 = __half22float2(ph[1]); \
                        float2 t2 = __half22float2(ph[2]); \
                        float2 t3 = __half22float2(ph[3]); \
                        a0.x += t0.x; a0.y += t0.y; \
                        a1.x += t1.x; a1.y += t1.y; \
                        a2.x += t2.x; a2.y += t2.y; \
                        a3.x += t3.x; a3.y += t3.y; } while (0)
                    ACCUM(q0); ACCUM(q1); ACCUM(q2); ACCUM(q3);
                    #undef ACCUM
                }
            }
            // cross-half reduce: lane li and li+16 hold same 8 cols (li*8..+7)
            a0.x += __shfl_xor_sync(0xffffffffu, a0.x, 16);
            a0.y += __shfl_xor_sync(0xffffffffu, a0.y, 16);
            a1.x += __shfl_xor_sync(0xffffffffu, a1.x, 16);
            a1.y += __shfl_xor_sync(0xffffffffu, a1.y, 16);
            a2.x += __shfl_xor_sync(0xffffffffu, a2.x, 16);
            a2.y += __shfl_xor_sync(0xffffffffu, a2.y, 16);
            a3.x += __shfl_xor_sync(0xffffffffu, a3.x, 16);
            a3.y += __shfl_xor_sync(0xffffffffu, a3.y, 16);

            float nmd = g_norm[row] * (1.0f - ALPHA);
            // lane handles 4 cols: half0 -> li*8+0..3 (a0,a1); half1 -> li*8+4..7 (a2,a3)
            float4 f0 = __ldg((const float4*)feat0 + (size_t)row * 32 + li * 2 + half);
            float4 v;
            if (half == 0) { v.x = a0.x; v.y = a0.y; v.z = a1.x; v.w = a1.y; }
            else           { v.x = a2.x; v.y = a2.y; v.z = a3.x; v.w = a3.y; }
            v.x = v.x * nmd + f0.x * ALPHA;
            v.y = v.y * nmd + f0.y * ALPHA;
            v.z = v.z * nmd + f0.z * ALPHA;
            v.w = v.w * nmd + f0.w * ALPHA;
            *(float4*)&sh[lrow][li * 8 + half * 4] = v;
        } else {
            *(float4*)&sh[lrow][li * 8 + half * 4] = make_float4(0.f, 0.f, 0.f, 0.f);
        }
    }
    __syncthreads();

    // ---- phase 2: MMA. warp -> (M-tile, N-quarter) ----
    const int mw = w & 3;
    const int nq = w >> 2;
    float acc[4][4];
    #pragma unroll
    for (int nt = 0; nt < 4; nt++)
        #pragma unroll
        for (int i = 0; i < 4; i++) acc[nt][i] = 0.f;

    const int ra = mw * 16 + (lane >> 2);
    const int ca = lane & 3;

    #pragma unroll
    for (int kt = 0; kt < 16; kt++) {
        unsigned a0 = f2tf32(sh[ra][kt * 8 + ca]);
        unsigned a1 = f2tf32(sh[ra + 8][kt * 8 + ca]);
        unsigned a2 = f2tf32(sh[ra][kt * 8 + ca + 4]);
        unsigned a3 = f2tf32(sh[ra + 8][kt * 8 + ca + 4]);
        const uint2* bp = g_wperm + (kt * 16 + nq * 4) * 32 + lane;
        #pragma unroll
        for (int nt = 0; nt < 4; nt++) {
            uint2 b = __ldg(bp + nt * 32);
            asm volatile(
                "mma.sync.aligned.m16n8k8.row.col.f32.tf32.tf32.f32 "
                "{%0,%1,%2,%3}, {%4,%5,%6,%7}, {%8,%9}, {%0,%1,%2,%3};"
                : "+f"(acc[nt][0]), "+f"(acc[nt][1]),
                  "+f"(acc[nt][2]), "+f"(acc[nt][3])
                : "r"(a0), "r"(a1), "r"(a2), "r"(a3), "r"(b.x), "r"(b.y));
        }
    }

    const int lr   = mw * 16 + (lane >> 2);
    const int row0 = r0 + lr;
    const int col0 = (lane & 3) * 2;
    #pragma unroll
    for (int nt = 0; nt < 4; nt++) {
        int col = nq * 32 + nt * 8 + col0;
        float b0 = __ldg(&bias[col]);
        float b1 = __ldg(&bias[col + 1]);
        if (row0 < n) {
            float2 o;
            o.x = ONE_MB * sh[lr][col]     + BETA * acc[nt][0] + b0;
            o.y = ONE_MB * sh[lr][col + 1] + BETA * acc[nt][1] + b1;
            *(float2*)&out[(size_t)row0 * D + col] = o;
        }
        if (row0 + 8 < n) {
            float2 o;
            o.x = ONE_MB * sh[lr + 8][col]     + BETA * acc[nt][2] + b0;
            o.y = ONE_MB * sh[lr + 8][col + 1] + BETA * acc[nt][3] + b1;
            *(float2*)&out[(size_t)(row0 + 8) * D + col] = o;
        }
    }
}

extern "C" void kernel_launch(void* const* d_in, const int* in_sizes, int n_in,
                              void* d_out, int out_size) {
    const float* feat  = (const float*)d_in[0];
    const float* feat0 = (const float*)d_in[1];
    const float* W     = (const float*)d_in[2];
    const float* bias  = (const float*)d_in[3];
    const int*   src   = (const int*)d_in[4];
    const int*   dst   = (const int*)d_in[5];
    float* out = (float*)d_out;

    int n  = in_sizes[0] / D;
    int ne = in_sizes[4];
    int nb = (n + SCAN_B - 1) / SCAN_B;          // 196 scan blocks

    int eb4 = (ne + 1023) / 1024;                 // 586 edge blocks
    int grid = eb4 > nb ? eb4 : nb;
    if (grid < 32) grid = 32;
    if (grid > 1184) grid = 1184;                 // co-residency cap (8 blk/SM x 148)

    prep_kernel<<<grid, 256>>>(src, dst, W, feat, ne, n, nb);
    fused_mma_kernel<<<(n + GROWS - 1) / GROWS, 512>>>(feat0, bias, out, n);
}